// round 13
// baseline (speedup 1.0000x reference)
#include <cuda_runtime.h>
#include <cstdint>

#define LL   2
#define TT   512
#define BB   128
#define HH   256
#define CLSZ 8
#define NCL  16
#define NTHR 512

// ---------------- smem layout (float indices) ----------------
#define OFF_U    0          // [128 col][260 pad h] tf32 bits   33280
#define OFF_HB   33280      // [2 grp][8 n][260 pad h]           4160
#define OFF_OUT  37440      // [2 grp][2 parity][128]             512
#define OFF_PRE  37952      // [2 kh][128 col][9 pad n]          2304
#define OFF_WX   40256      // [128 col][4 f]                     512
#define OFF_WB   40768      // [128 col]                          128
#define OFF_FW   40896      // [256 k][4 f]                      1024
#define OFF_FB   41920      // [4]                                  4
#define OFF_FLAG 41924      // [2 grp][8] int flags                16
#define SMEM_FLOATS 41940
#define SMEM_BYTES (SMEM_FLOATS * 4)

// layer-1 output scratch, TRANSPOSED: [B][T][4]
__device__ float g_y1[BB * TT * 4];

typedef unsigned long long ull;

__device__ __forceinline__ uint32_t smem_u32(const void* p) {
    uint32_t a;
    asm("{ .reg .u64 t; cvta.to.shared.u64 t, %1; cvt.u32.u64 %0, t; }"
        : "=r"(a) : "l"(p));
    return a;
}
__device__ __forceinline__ void cluster_sync() {
    asm volatile("barrier.cluster.arrive.aligned;" ::: "memory");
    asm volatile("barrier.cluster.wait.aligned;" ::: "memory");
}
__device__ __forceinline__ float fsig(float x) {
    float e, r;
    asm("ex2.approx.f32 %0, %1;" : "=f"(e) : "f"(x * -1.4426950408889634f));
    asm("rcp.approx.f32 %0, %1;" : "=f"(r) : "f"(1.0f + e));
    return r;
}
__device__ __forceinline__ float ftanh(float x) {
    float e, r;
    asm("ex2.approx.f32 %0, %1;" : "=f"(e) : "f"(x * -2.8853900817779268f));
    asm("rcp.approx.f32 %0, %1;" : "=f"(r) : "f"(1.0f + e));
    return __fmaf_rn(2.0f, r, -1.0f);
}
__device__ __forceinline__ uint32_t f2tf32(float x) {
    uint32_t u;
    asm("cvt.rna.tf32.f32 %0, %1;" : "=r"(u) : "f"(x));
    return u;
}
__device__ __forceinline__ void flag_spin(uint32_t fa, int target) {
    int v;
    do {
        asm volatile("ld.volatile.shared.b32 %0, [%1];" : "=r"(v) : "r"(fa));
    } while (v < target);
}
__device__ __forceinline__ void mma_tf32(float& d0, float& d1, float& d2, float& d3,
                                         uint32_t a0, uint32_t a1, uint32_t a2, uint32_t a3,
                                         uint32_t b0, uint32_t b1) {
    asm("mma.sync.aligned.m16n8k8.row.col.f32.tf32.tf32.f32 "
        "{%0,%1,%2,%3},{%4,%5,%6,%7},{%8,%9},{%0,%1,%2,%3};"
        : "+f"(d0), "+f"(d1), "+f"(d2), "+f"(d3)
        : "r"(a0), "r"(a1), "r"(a2), "r"(a3), "r"(b0), "r"(b1));
}

#define QNEG_MASK 0x284E

__global__ void __launch_bounds__(NTHR, 1) __cluster_dims__(CLSZ, 1, 1)
qlstm_kernel(const float* __restrict__ x,
             const float* __restrict__ Wxr, const float* __restrict__ Wxi,
             const float* __restrict__ Wxj, const float* __restrict__ Wxk,
             const float* __restrict__ Wxb,
             const float* __restrict__ Ur,  const float* __restrict__ Ui,
             const float* __restrict__ Uj,  const float* __restrict__ Uk,
             const float* __restrict__ fcw, const float* __restrict__ fcb,
             float* __restrict__ out)
{
    extern __shared__ float sm[];
    float* sU   = sm + OFF_U;
    float* sHB  = sm + OFF_HB;     // + g*2080
    float* sOut = sm + OFF_OUT;    // + (g*2+parity)*128
    float* sPre = sm + OFF_PRE;
    float* sWx  = sm + OFF_WX;
    float* sWb  = sm + OFF_WB;
    float* sFW  = sm + OFF_FW;
    float* sFB  = sm + OFF_FB;

    const int tid  = threadIdx.x;
    const int lane = tid & 31;
    const int wid  = tid >> 5;
    const int r    = blockIdx.x & 7;
    const int cid  = blockIdx.x >> 3;
    const uint32_t sbase = smem_u32(sm);

    // mma role: warp = (col-tile ct 0..7, K-half kh 0..1)
    const int ct = wid & 7;
    const int kh = wid >> 3;
    const int mr = lane >> 2;
    const int mc = lane & 3;

    // act role (warps 0..3): batch-within-group = wid, k = lane
    const int k = lane;

    // pull role: 64 threads per source rank, 2 floats each
    const int pj  = wid >> 1;          // source rank (warp-uniform)
    const int rem = tid & 63;
    const int pbd = rem >> 4;          // dest batch row 0..3
    const int phl = (rem * 2) & 31;    // dest h offset within 32-chunk
    // own batch for y: group + index
    const int ga = r >> 2;
    const int ba = r & 3;

    // ---- one-time init ----
    if (tid < 16) ((int*)(sm + OFF_FLAG))[tid] = 0;
    __syncthreads();
    cluster_sync();

    float2 creg;   // c-state: x = group0 cell, y = group1 cell (thread tid<128)

    for (int l = 0; l < LL; l++) {
        __syncthreads();

        // ---- gather U slice (tf32), sU[col][260 pad h] ----
        for (int idx = tid; idx < 4 * 256 * 32; idx += NTHR) {
            int g   = idx >> 13;
            int rem2 = idx & 8191;
            int h   = rem2 >> 5;
            int kl  = rem2 & 31;
            int kg  = r * 32 + kl;
            int hb  = h >> 6, n = h & 63;
            int cb  = kg >> 6, m = kg & 63;
            int sel = hb ^ cb;
            float sgn = ((QNEG_MASK >> (cb * 4 + hb)) & 1) ? -1.0f : 1.0f;
            const float* cp = (sel == 0) ? Ur : (sel == 1) ? Ui : (sel == 2) ? Uj : Uk;
            float v = sgn * __ldg(&cp[((l * 4 + g) * 64 + n) * 64 + m]);
            sU[(g * 32 + kl) * 260 + h] = __uint_as_float(f2tf32(v));
        }
        for (int idx = tid; idx < 512; idx += NTHR) {
            int g  = idx >> 7;
            int f  = (idx >> 5) & 3;
            int kl = idx & 31;
            int kg = r * 32 + kl;
            int cb = kg >> 6, m = kg & 63;
            int sel = f ^ cb;
            float sgn = ((QNEG_MASK >> (cb * 4 + f)) & 1) ? -1.0f : 1.0f;
            const float* cp = (sel == 0) ? Wxr : (sel == 1) ? Wxi : (sel == 2) ? Wxj : Wxk;
            sWx[(g * 32 + kl) * 4 + f] = sgn * __ldg(&cp[(l * 4 + g) * 64 + m]);
        }
        for (int idx = tid; idx < 128; idx += NTHR) {
            int g = idx >> 5, kl = idx & 31;
            sWb[idx] = Wxb[(l * 4 + g) * 256 + r * 32 + kl];
        }
        for (int idx = tid; idx < 1024; idx += NTHR)
            sFW[idx] = fcw[l * 1024 + idx];
        if (tid < 4) sFB[tid] = fcb[l * 4 + tid];
        // zero both h-group buffers (rows 4..7 stay zero forever)
        for (int i = tid; i < 2 * 2080; i += NTHR) sHB[i] = 0.0f;
        creg = make_float2(0.0f, 0.0f);
        __syncthreads();

        // ---- preload U A-fragments (per layer) ----
        uint32_t Afr[16][4];
        {
            const int row0 = ct * 16 + mr;
            const int kb0  = kh * 128 + mc;
#pragma unroll
            for (int kt = 0; kt < 16; kt++) {
                int kb = kb0 + kt * 8;
                Afr[kt][0] = __float_as_uint(sU[row0 * 260 + kb]);
                Afr[kt][1] = __float_as_uint(sU[(row0 + 8) * 260 + kb]);
                Afr[kt][2] = __float_as_uint(sU[row0 * 260 + kb + 4]);
                Afr[kt][3] = __float_as_uint(sU[(row0 + 8) * 260 + kb + 4]);
            }
        }

        const float4* xp = (const float4*)((l == 0) ? x : g_y1);  // [B][T][4]

        // ================= pipelined step loop: groups alternate =================
        auto iter = [&](int t, int g) {
            float* hbg = sHB + g * 2080;

            // ---- pull h_t for this group (published end of iter t-1,g) ----
            if (t > 0) {
                const int target = l * TT + t;
                if (lane == 0)
                    flag_spin(sbase + (OFF_FLAG + g * 8 + pj) * 4, target);
                __syncwarp();
                const int parity = (t - 1) & 1;
                const uint32_t so = sbase +
                    (uint32_t)(OFF_OUT + (g * 2 + parity) * 128 + rem * 2) * 4;
                uint32_t ra;
                asm("mapa.shared::cluster.u32 %0, %1, %2;"
                    : "=r"(ra) : "r"(so), "r"(pj));
                ull v;
                asm volatile("ld.shared::cluster.b64 %0, [%1];"
                             : "=l"(v) : "r"(ra) : "memory");
                asm volatile("st.shared.b64 [%0], %1;"
                             :: "r"(sbase + (uint32_t)(OFF_HB + g * 2080 +
                                    pbd * 260 + pj * 32 + phl) * 4),
                                "l"(v) : "memory");
            }
            __syncthreads();   // sHB_g = h_t complete

            // ---- tensor GEMM: D[16c x 8n] (n 0..3 real) ----
            {
                float dA0 = 0.f, dA1 = 0.f, dA2 = 0.f, dA3 = 0.f;
                float dB0 = 0.f, dB1 = 0.f, dB2 = 0.f, dB3 = 0.f;
                const float* bp = hbg + mr * 260 + kh * 128 + mc;
#pragma unroll
                for (int kt = 0; kt < 8; kt++) {
                    uint32_t bb0 = __float_as_uint(bp[kt * 8]);
                    uint32_t bb1 = __float_as_uint(bp[kt * 8 + 4]);
                    mma_tf32(dA0, dA1, dA2, dA3,
                             Afr[kt][0], Afr[kt][1], Afr[kt][2], Afr[kt][3], bb0, bb1);
                }
#pragma unroll
                for (int kt = 8; kt < 16; kt++) {
                    uint32_t bb0 = __float_as_uint(bp[kt * 8]);
                    uint32_t bb1 = __float_as_uint(bp[kt * 8 + 4]);
                    mma_tf32(dB0, dB1, dB2, dB3,
                             Afr[kt][0], Afr[kt][1], Afr[kt][2], Afr[kt][3], bb0, bb1);
                }
                const int colA = ct * 16 + mr;
                const int nn   = mc * 2;
                float* p0 = sPre + kh * 1152 + colA * 9 + nn;
                float* p1 = sPre + kh * 1152 + (colA + 8) * 9 + nn;
                p0[0] = dA0 + dB0; p0[1] = dA1 + dB1;
                p1[0] = dA2 + dB2; p1[1] = dA3 + dB3;
            }
            __syncthreads();   // sPre ready

            // ---- act (warps 0..3: batch-within-group = wid) ----
            if (tid < 128) {
                const int w  = wid;
                const int gb = g * 4 + w;            // batch within cluster
                float4 xv = __ldg(&xp[(cid * 8 + gb) * TT + t]);
                float pre[4];
#pragma unroll
                for (int gt = 0; gt < 4; gt++) {
                    int col = gt * 32 + k;
                    float4 wx = *(const float4*)&sWx[col * 4];
                    float wb  = sWb[col];
                    float base = sPre[col * 9 + w] + sPre[1152 + col * 9 + w];
                    pre[gt] = base + wb + xv.x * wx.x + xv.y * wx.y
                                        + xv.z * wx.z + xv.w * wx.w;
                }
                float ft = fsig(pre[0]), it = fsig(pre[1]);
                float ot = fsig(pre[2]), cc = ftanh(pre[3]);
                float cold = g ? creg.y : creg.x;
                float c = it * cc + ft * cold;
                if (g) creg.y = c; else creg.x = c;
                float hn = ot * ftanh(c);
                sOut[(g * 2 + (t & 1)) * 128 + w * 32 + k] =
                    __uint_as_float(f2tf32(hn));
            }

            // ---- y-warp: y_{t-1} for own batch (layer 0, own group) ----
            if (l == 0 && wid == 15 && g == ga && t > 0) {
                float s0 = 0.f, s1 = 0.f, s2 = 0.f, s3 = 0.f;
#pragma unroll
                for (int i = 0; i < 8; i++) {
                    int kk = lane + i * 32;
                    float hv = hbg[ba * 260 + kk];
                    float4 fw = *(const float4*)&sFW[kk * 4];
                    s0 += hv * fw.x; s1 += hv * fw.y;
                    s2 += hv * fw.z; s3 += hv * fw.w;
                }
#pragma unroll
                for (int m = 16; m >= 1; m >>= 1) {
                    s0 += __shfl_xor_sync(0xffffffffu, s0, m);
                    s1 += __shfl_xor_sync(0xffffffffu, s1, m);
                    s2 += __shfl_xor_sync(0xffffffffu, s2, m);
                    s3 += __shfl_xor_sync(0xffffffffu, s3, m);
                }
                if (lane == 0) {
                    s0 += sFB[0]; s1 += sFB[1]; s2 += sFB[2]; s3 += sFB[3];
                    float nn = s0 * s0 + s1 * s1 + s2 * s2 + s3 * s3;
                    float iv = 1.0f / fmaxf(sqrtf(nn), 1e-12f);
                    ((float4*)g_y1)[(cid * 8 + r) * TT + (t - 1)] =
                        make_float4(s0 * iv, s1 * iv, s2 * iv, s3 * iv);
                }
            }
            __syncthreads();   // sOut drained

            // ---- publish this group's flag to all 8 ranks ----
            if (tid == 0) {
                const int gs = l * TT + t + 1;
                uint32_t fa = sbase + (OFF_FLAG + g * 8 + r) * 4;
#pragma unroll
                for (int j = 0; j < CLSZ; j++) {
                    uint32_t ra;
                    asm("mapa.shared::cluster.u32 %0, %1, %2;"
                        : "=r"(ra) : "r"(fa), "r"(j));
                    asm volatile("st.shared::cluster.b32 [%0], %1;"
                                 :: "r"(ra), "r"(gs) : "memory");
                }
            }
        };

        for (int t = 0; t < TT; t++) {
            iter(t, 0);
            iter(t, 1);
        }

        // ---- final exchange: pull h_T for both groups, compute y_{T-1} ----
        {
            const int target = (l + 1) * TT;
#pragma unroll
            for (int g = 0; g < 2; g++) {
                if (lane == 0)
                    flag_spin(sbase + (OFF_FLAG + g * 8 + pj) * 4, target);
                __syncwarp();
                const int parity = (TT - 1) & 1;
                const uint32_t so = sbase +
                    (uint32_t)(OFF_OUT + (g * 2 + parity) * 128 + rem * 2) * 4;
                uint32_t ra;
                asm("mapa.shared::cluster.u32 %0, %1, %2;"
                    : "=r"(ra) : "r"(so), "r"(pj));
                ull v;
                asm volatile("ld.shared::cluster.b64 %0, [%1];"
                             : "=l"(v) : "r"(ra) : "memory");
                asm volatile("st.shared.b64 [%0], %1;"
                             :: "r"(sbase + (uint32_t)(OFF_HB + g * 2080 +
                                    pbd * 260 + pj * 32 + phl) * 4),
                                "l"(v) : "memory");
            }
        }
        __syncthreads();

        if (wid == 15) {
            const float* hbg = sHB + ga * 2080;
            float s0 = 0.f, s1 = 0.f, s2 = 0.f, s3 = 0.f;
#pragma unroll
            for (int i = 0; i < 8; i++) {
                int kk = lane + i * 32;
                float hv = hbg[ba * 260 + kk];
                float4 fw = *(const float4*)&sFW[kk * 4];
                s0 += hv * fw.x; s1 += hv * fw.y;
                s2 += hv * fw.z; s3 += hv * fw.w;
            }
#pragma unroll
            for (int m = 16; m >= 1; m >>= 1) {
                s0 += __shfl_xor_sync(0xffffffffu, s0, m);
                s1 += __shfl_xor_sync(0xffffffffu, s1, m);
                s2 += __shfl_xor_sync(0xffffffffu, s2, m);
                s3 += __shfl_xor_sync(0xffffffffu, s3, m);
            }
            if (lane == 0) {
                s0 += sFB[0]; s1 += sFB[1]; s2 += sFB[2]; s3 += sFB[3];
                float nn = s0 * s0 + s1 * s1 + s2 * s2 + s3 * s3;
                float iv = 1.0f / fmaxf(sqrtf(nn), 1e-12f);
                if (l == 0) {
                    ((float4*)g_y1)[(cid * 8 + r) * TT + (TT - 1)] =
                        make_float4(s0 * iv, s1 * iv, s2 * iv, s3 * iv);
                } else {
                    ((float4*)out)[cid * 8 + r] =
                        make_float4(s0 * iv, s1 * iv, s2 * iv, s3 * iv);
                }
            }
        }
        cluster_sync();   // g_y1 visible before next layer reads it
    } // l

    cluster_sync();
}

extern "C" void kernel_launch(void* const* d_in, const int* in_sizes, int n_in,
                              void* d_out, int out_size)
{
    (void)in_sizes; (void)n_in; (void)out_size;
    cudaFuncSetAttribute(qlstm_kernel,
                         cudaFuncAttributeMaxDynamicSharedMemorySize, SMEM_BYTES);
    qlstm_kernel<<<NCL * CLSZ, NTHR, SMEM_BYTES>>>(
        (const float*)d_in[0],
        (const float*)d_in[1], (const float*)d_in[2],
        (const float*)d_in[3], (const float*)d_in[4],
        (const float*)d_in[5],
        (const float*)d_in[6], (const float*)d_in[7],
        (const float*)d_in[8], (const float*)d_in[9],
        (const float*)d_in[10], (const float*)d_in[11],
        (float*)d_out);
}

// round 14
// speedup vs baseline: 1.0322x; 1.0322x over previous
#include <cuda_runtime.h>
#include <cstdint>

#define LL   2
#define TT   512
#define BB   128
#define CLSZ 8
#define NCL  16
#define NTHR 512

// ---------------- smem layout (float indices) ----------------
#define OFF_UF   0          // [8 ct][32 kt][32 lane][4] tf32   32768
#define OFF_HB   32768      // [2 parity][8 n][260 pad h]        4160
#define OFF_OUT  36928      // [2 parity][8 b * 32 k]             512
#define OFF_WX   37440      // [128 row'][4 f]                    512
#define OFF_WB   37952      // [128 row']                         128
#define OFF_FW   38080      // [256 k][4 f]                      1024
#define OFF_FB   39104      // [4]                                  4
#define OFF_FLAG 39108      // [8] int step flags                   8
#define SMEM_FLOATS 39116
#define SMEM_BYTES (SMEM_FLOATS * 4)

// layer-1 output scratch, TRANSPOSED: [B][T][4]
__device__ float g_y1[BB * TT * 4];

typedef unsigned long long ull;

__device__ __forceinline__ uint32_t smem_u32(const void* p) {
    uint32_t a;
    asm("{ .reg .u64 t; cvta.to.shared.u64 t, %1; cvt.u32.u64 %0, t; }"
        : "=r"(a) : "l"(p));
    return a;
}
__device__ __forceinline__ void cluster_sync() {
    asm volatile("barrier.cluster.arrive.aligned;" ::: "memory");
    asm volatile("barrier.cluster.wait.aligned;" ::: "memory");
}
__device__ __forceinline__ float fsig(float x) {
    float e, r;
    asm("ex2.approx.f32 %0, %1;" : "=f"(e) : "f"(x * -1.4426950408889634f));
    asm("rcp.approx.f32 %0, %1;" : "=f"(r) : "f"(1.0f + e));
    return r;
}
__device__ __forceinline__ float ftanh(float x) {
    float e, r;
    asm("ex2.approx.f32 %0, %1;" : "=f"(e) : "f"(x * -2.8853900817779268f));
    asm("rcp.approx.f32 %0, %1;" : "=f"(r) : "f"(1.0f + e));
    return __fmaf_rn(2.0f, r, -1.0f);
}
__device__ __forceinline__ uint32_t f2tf32(float x) {
    uint32_t u;
    asm("cvt.rna.tf32.f32 %0, %1;" : "=r"(u) : "f"(x));
    return u;
}
__device__ __forceinline__ void flag_spin(uint32_t fa, int target) {
    int v;
    do {
        asm volatile("ld.volatile.shared.b32 %0, [%1];" : "=r"(v) : "r"(fa));
    } while (v < target);
}
__device__ __forceinline__ void mma_tf32(float& d0, float& d1, float& d2, float& d3,
                                         uint32_t a0, uint32_t a1, uint32_t a2, uint32_t a3,
                                         uint32_t b0, uint32_t b1) {
    asm("mma.sync.aligned.m16n8k8.row.col.f32.tf32.tf32.f32 "
        "{%0,%1,%2,%3},{%4,%5,%6,%7},{%8,%9},{%0,%1,%2,%3};"
        : "+f"(d0), "+f"(d1), "+f"(d2), "+f"(d3)
        : "r"(a0), "r"(a1), "r"(a2), "r"(a3), "r"(b0), "r"(b1));
}

#define QNEG_MASK 0x284E

__global__ void __launch_bounds__(NTHR, 1) __cluster_dims__(CLSZ, 1, 1)
qlstm_kernel(const float* __restrict__ x,
             const float* __restrict__ Wxr, const float* __restrict__ Wxi,
             const float* __restrict__ Wxj, const float* __restrict__ Wxk,
             const float* __restrict__ Wxb,
             const float* __restrict__ Ur,  const float* __restrict__ Ui,
             const float* __restrict__ Uj,  const float* __restrict__ Uk,
             const float* __restrict__ fcw, const float* __restrict__ fcb,
             float* __restrict__ out)
{
    extern __shared__ float sm[];
    float* sUf  = sm + OFF_UF;
    float* sHB  = sm + OFF_HB;     // + parity*2080
    float* sOut = sm + OFF_OUT;    // + parity*256
    float* sWx  = sm + OFF_WX;
    float* sWb  = sm + OFF_WB;
    float* sFW  = sm + OFF_FW;
    float* sFB  = sm + OFF_FB;

    const int tid  = threadIdx.x;
    const int lane = tid & 31;
    const int wid  = tid >> 5;
    const int r    = blockIdx.x & 7;
    const int cid  = blockIdx.x >> 3;
    const uint32_t sbase = smem_u32(sm);

    // MMA warp role (wid 0..7): tile ct = wid; fragment coords
    const int ct = wid;            // valid for wid<8
    const int mr = lane >> 2;      // fragment row group 0..7
    const int mc = lane & 3;       // fragment col group 0..3
    const int n0 = mc * 2;         // batch pair
    const int n1 = n0 + 1;

    // pull warp role (wid 8..15): source rank j
    const int pj = wid - 8;

    // y role: own batch = cid*8 + r
    // ---- one-time init ----
    if (tid < 8) ((int*)(sm + OFF_FLAG))[tid] = 0;
    __syncthreads();
    cluster_sync();

    float2 creg = make_float2(0.f, 0.f);  // lanes<16 of MMA warps: c-state (2 batches)

    for (int l = 0; l < LL; l++) {
        __syncthreads();   // previous layer fully done locally

        // ---- gather U into fragment-native layout (tf32) ----
        // sUf[((ct*32 + kt)*32 + lane)*4 + a]:
        //   a0: (row0, k0)  a1: (row0+8, k0)  a2: (row0, k0+4)  a3: (row0+8, k0+4)
        // row' = ct*16 + gate*4 + c  maps logical col = gate*32 + (ct*4 + c)
        for (int idx = tid; idx < 32768; idx += NTHR) {
            int a  = idx & 3;
            int li = (idx >> 2) & 31;
            int kt = (idx >> 7) & 31;
            int c2 = idx >> 12;                 // ct
            int rowp = c2 * 16 + (li >> 2) + (a & 1) * 8;
            int kdim = kt * 8 + (li & 3) + ((a >> 1) & 1) * 4;
            int sub  = rowp & 15;
            int gate = sub >> 2;
            int cc   = sub & 3;
            int kl   = c2 * 4 + cc;
            int kg   = r * 32 + kl;
            int hb   = kdim >> 6, n = kdim & 63;
            int cb   = kg >> 6,  m = kg & 63;
            int sel  = hb ^ cb;
            float sgn = ((QNEG_MASK >> (cb * 4 + hb)) & 1) ? -1.0f : 1.0f;
            const float* cp = (sel == 0) ? Ur : (sel == 1) ? Ui : (sel == 2) ? Uj : Uk;
            float v = sgn * __ldg(&cp[((l * 4 + gate) * 64 + n) * 64 + m]);
            sUf[idx] = __uint_as_float(f2tf32(v));
        }
        // ---- Wx/Wb in permuted row' order ----
        for (int idx = tid; idx < 512; idx += NTHR) {
            int rowp = idx >> 2;
            int f    = idx & 3;
            int sub  = rowp & 15;
            int gate = sub >> 2;
            int cc   = sub & 3;
            int kl   = (rowp >> 4) * 4 + cc;
            int kg   = r * 32 + kl;
            int cb   = kg >> 6, m = kg & 63;
            int sel  = f ^ cb;
            float sgn = ((QNEG_MASK >> (cb * 4 + f)) & 1) ? -1.0f : 1.0f;
            const float* cp = (sel == 0) ? Wxr : (sel == 1) ? Wxi : (sel == 2) ? Wxj : Wxk;
            sWx[idx] = sgn * __ldg(&cp[(l * 4 + gate) * 64 + m]);
        }
        for (int idx = tid; idx < 128; idx += NTHR) {
            int sub  = idx & 15;
            int gate = sub >> 2;
            int kl   = (idx >> 4) * 4 + (sub & 3);
            sWb[idx] = Wxb[(l * 4 + gate) * 256 + r * 32 + kl];
        }
        for (int idx = tid; idx < 1024; idx += NTHR)
            sFW[idx] = fcw[l * 1024 + idx];
        if (tid < 4) sFB[tid] = fcb[l * 4 + tid];
        // zero both h parity buffers (h_0 = 0)
        for (int i = tid; i < 2 * 2080; i += NTHR) sHB[i] = 0.0f;
        creg = make_float2(0.f, 0.f);
        __syncthreads();

        const float4* xp = (const float4*)((l == 0) ? x : g_y1);  // [B][T][4]

        // per-layer constant regs for MMA warps
        float4 wxr0, wxr1; float wb0v = 0.f, wb1v = 0.f;
        if (wid < 8) {
            int row0p = ct * 16 + mr;
            wxr0 = *(const float4*)&sWx[row0p * 4];
            wxr1 = *(const float4*)&sWx[(row0p + 8) * 4];
            wb0v = sWb[row0p];
            wb1v = sWb[row0p + 8];
        }

        for (int t = 0; t < TT; t++) {
            const int cur = t & 1;
            const int nxt = cur ^ 1;

            if (wid < 8) {
                // ---- x loads early (latency hidden under MMA) ----
                float4 xv0 = __ldg(&xp[(cid * 8 + n0) * TT + t]);
                float4 xv1 = __ldg(&xp[(cid * 8 + n1) * TT + t]);

                // ---- MMA: D[16 row' x 8 n] over K=256, A from sUf (LDS.128) ----
                float d00=0.f,d01=0.f,d02=0.f,d03=0.f;
                float d10=0.f,d11=0.f,d12=0.f,d13=0.f;
                float d20=0.f,d21=0.f,d22=0.f,d23=0.f;
                float d30=0.f,d31=0.f,d32=0.f,d33=0.f;
                const float* ap = sUf + ct * 4096 + lane * 4;
                const float* bp = sHB + cur * 2080 + mr * 260 + mc;
#pragma unroll
                for (int kt = 0; kt < 32; kt += 4) {
                    float4 a0 = *(const float4*)(ap + kt * 128);
                    float4 a1 = *(const float4*)(ap + (kt + 1) * 128);
                    float4 a2 = *(const float4*)(ap + (kt + 2) * 128);
                    float4 a3 = *(const float4*)(ap + (kt + 3) * 128);
                    uint32_t b00 = __float_as_uint(bp[kt * 8]);
                    uint32_t b01 = __float_as_uint(bp[kt * 8 + 4]);
                    uint32_t b10 = __float_as_uint(bp[kt * 8 + 8]);
                    uint32_t b11 = __float_as_uint(bp[kt * 8 + 12]);
                    uint32_t b20 = __float_as_uint(bp[kt * 8 + 16]);
                    uint32_t b21 = __float_as_uint(bp[kt * 8 + 20]);
                    uint32_t b30 = __float_as_uint(bp[kt * 8 + 24]);
                    uint32_t b31 = __float_as_uint(bp[kt * 8 + 28]);
                    mma_tf32(d00,d01,d02,d03,
                             __float_as_uint(a0.x), __float_as_uint(a0.y),
                             __float_as_uint(a0.z), __float_as_uint(a0.w), b00, b01);
                    mma_tf32(d10,d11,d12,d13,
                             __float_as_uint(a1.x), __float_as_uint(a1.y),
                             __float_as_uint(a1.z), __float_as_uint(a1.w), b10, b11);
                    mma_tf32(d20,d21,d22,d23,
                             __float_as_uint(a2.x), __float_as_uint(a2.y),
                             __float_as_uint(a2.z), __float_as_uint(a2.w), b20, b21);
                    mma_tf32(d30,d31,d32,d33,
                             __float_as_uint(a3.x), __float_as_uint(a3.y),
                             __float_as_uint(a3.z), __float_as_uint(a3.w), b30, b31);
                }
                float D0 = (d00 + d10) + (d20 + d30);   // (row0,  n0)
                float D1 = (d01 + d11) + (d21 + d31);   // (row0,  n1)
                float D2 = (d02 + d12) + (d22 + d32);   // (row0+8,n0)
                float D3 = (d03 + d13) + (d23 + d33);   // (row0+8,n1)

                // ---- pre-activations (add bias + x·Wx) ----
                float p00 = D0 + wb0v + xv0.x*wxr0.x + xv0.y*wxr0.y + xv0.z*wxr0.z + xv0.w*wxr0.w;
                float p01 = D1 + wb0v + xv1.x*wxr0.x + xv1.y*wxr0.y + xv1.z*wxr0.z + xv1.w*wxr0.w;
                float p10 = D2 + wb1v + xv0.x*wxr1.x + xv0.y*wxr1.y + xv0.z*wxr1.z + xv0.w*wxr1.w;
                float p11 = D3 + wb1v + xv1.x*wxr1.x + xv1.y*wxr1.y + xv1.z*wxr1.z + xv1.w*wxr1.w;

                // ---- exchange gate halves: lanes<16 own (f,o), partner has (i,c~) ----
                float q00 = __shfl_xor_sync(0xffffffffu, p00, 16);
                float q01 = __shfl_xor_sync(0xffffffffu, p01, 16);
                float q10 = __shfl_xor_sync(0xffffffffu, p10, 16);
                float q11 = __shfl_xor_sync(0xffffffffu, p11, 16);

                if (lane < 16) {
                    // this lane: cell = ct*4 + mr (mr<4), batches n0,n1
                    {
                        float ft = fsig(p00), it = fsig(q00);
                        float ot = fsig(p10), cc = ftanh(q10);
                        float c = it * cc + ft * creg.x;
                        creg.x = c;
                        float hn = ot * ftanh(c);
                        sOut[cur * 256 + n0 * 32 + ct * 4 + mr] =
                            __uint_as_float(f2tf32(hn));
                    }
                    {
                        float ft = fsig(p01), it = fsig(q01);
                        float ot = fsig(p11), cc = ftanh(q11);
                        float c = it * cc + ft * creg.y;
                        creg.y = c;
                        float hn = ot * ftanh(c);
                        sOut[cur * 256 + n1 * 32 + ct * 4 + mr] =
                            __uint_as_float(f2tf32(hn));
                    }
                }
                // drain STS among MMA warps, then publish
                asm volatile("bar.sync 1, 256;" ::: "memory");
                if (wid == 0 && lane == 0) {
                    const int gs = l * TT + t + 1;
                    uint32_t fa = sbase + (OFF_FLAG + r) * 4;
#pragma unroll
                    for (int j = 0; j < CLSZ; j++) {
                        uint32_t ra;
                        asm("mapa.shared::cluster.u32 %0, %1, %2;"
                            : "=r"(ra) : "r"(fa), "r"(j));
                        asm volatile("st.shared::cluster.b32 [%0], %1;"
                                     :: "r"(ra), "r"(gs) : "memory");
                    }
                }
            } else {
                // ---- y-warp: y_{t-1} (layer 0) overlaps MMA ----
                if (l == 0 && wid == 15 && t > 0) {
                    const float* hb = sHB + cur * 2080;
                    float s0 = 0.f, s1 = 0.f, s2 = 0.f, s3 = 0.f;
#pragma unroll
                    for (int i = 0; i < 8; i++) {
                        int kk = lane + i * 32;
                        float hv = hb[(r & 7) * 260 + kk];
                        float4 fw = *(const float4*)&sFW[kk * 4];
                        s0 += hv * fw.x; s1 += hv * fw.y;
                        s2 += hv * fw.z; s3 += hv * fw.w;
                    }
#pragma unroll
                    for (int m = 16; m >= 1; m >>= 1) {
                        s0 += __shfl_xor_sync(0xffffffffu, s0, m);
                        s1 += __shfl_xor_sync(0xffffffffu, s1, m);
                        s2 += __shfl_xor_sync(0xffffffffu, s2, m);
                        s3 += __shfl_xor_sync(0xffffffffu, s3, m);
                    }
                    if (lane == 0) {
                        s0 += sFB[0]; s1 += sFB[1]; s2 += sFB[2]; s3 += sFB[3];
                        float nn = s0*s0 + s1*s1 + s2*s2 + s3*s3;
                        float iv = 1.0f / fmaxf(sqrtf(nn), 1e-12f);
                        ((float4*)g_y1)[(cid * 8 + r) * TT + (t - 1)] =
                            make_float4(s0*iv, s1*iv, s2*iv, s3*iv);
                    }
                }
                // ---- pull warp: rank pj, as soon as it publishes step t ----
                const int target = l * TT + t + 1;
                if (lane == 0)
                    flag_spin(sbase + (OFF_FLAG + pj) * 4, target);
                __syncwarp();
#pragma unroll
                for (int q = 0; q < 4; q++) {
                    int idx = lane + 32 * q;          // 0..127 b64 units
                    int b   = idx >> 4;
                    int ko  = (idx & 15) * 2;
                    uint32_t so = sbase +
                        (uint32_t)(OFF_OUT + cur * 256 + b * 32 + ko) * 4;
                    uint32_t ra;
                    asm("mapa.shared::cluster.u32 %0, %1, %2;"
                        : "=r"(ra) : "r"(so), "r"(pj));
                    ull v;
                    asm volatile("ld.shared::cluster.b64 %0, [%1];"
                                 : "=l"(v) : "r"(ra) : "memory");
                    asm volatile("st.shared.b64 [%0], %1;"
                                 :: "r"(sbase + (uint32_t)(OFF_HB + nxt * 2080 +
                                        b * 260 + pj * 32 + ko) * 4),
                                    "l"(v) : "memory");
                }
            }
            __syncthreads();   // sHB[nxt] = h_{t+1} complete; sOut safe to reuse next parity
        } // t

        // ---- final y from h_T (sHB[TT&1 = 0]) ----
        if (wid == 15) {
            const float* hb = sHB + (TT & 1) * 2080;
            float s0 = 0.f, s1 = 0.f, s2 = 0.f, s3 = 0.f;
#pragma unroll
            for (int i = 0; i < 8; i++) {
                int kk = lane + i * 32;
                float hv = hb[r * 260 + kk];
                float4 fw = *(const float4*)&sFW[kk * 4];
                s0 += hv * fw.x; s1 += hv * fw.y;
                s2 += hv * fw.z; s3 += hv * fw.w;
            }
#pragma unroll
            for (int m = 16; m >= 1; m >>= 1) {
                s0 += __shfl_xor_sync(0xffffffffu, s0, m);
                s1 += __shfl_xor_sync(0xffffffffu, s1, m);
                s2 += __shfl_xor_sync(0xffffffffu, s2, m);
                s3 += __shfl_xor_sync(0xffffffffu, s3, m);
            }
            if (lane == 0) {
                s0 += sFB[0]; s1 += sFB[1]; s2 += sFB[2]; s3 += sFB[3];
                float nn = s0*s0 + s1*s1 + s2*s2 + s3*s3;
                float iv = 1.0f / fmaxf(sqrtf(nn), 1e-12f);
                if (l == 0) {
                    ((float4*)g_y1)[(cid * 8 + r) * TT + (TT - 1)] =
                        make_float4(s0*iv, s1*iv, s2*iv, s3*iv);
                } else {
                    ((float4*)out)[cid * 8 + r] =
                        make_float4(s0*iv, s1*iv, s2*iv, s3*iv);
                }
            }
        }
        cluster_sync();   // g_y1 (written by peers) visible before next layer
    } // l

    cluster_sync();   // no CTA exits while peers may still touch its SMEM
}

extern "C" void kernel_launch(void* const* d_in, const int* in_sizes, int n_in,
                              void* d_out, int out_size)
{
    (void)in_sizes; (void)n_in; (void)out_size;
    cudaFuncSetAttribute(qlstm_kernel,
                         cudaFuncAttributeMaxDynamicSharedMemorySize, SMEM_BYTES);
    qlstm_kernel<<<NCL * CLSZ, NTHR, SMEM_BYTES>>>(
        (const float*)d_in[0],
        (const float*)d_in[1], (const float*)d_in[2],
        (const float*)d_in[3], (const float*)d_in[4],
        (const float*)d_in[5],
        (const float*)d_in[6], (const float*)d_in[7],
        (const float*)d_in[8], (const float*)d_in[9],
        (const float*)d_in[10], (const float*)d_in[11],
        (float*)d_out);
}

// round 15
// speedup vs baseline: 1.4818x; 1.4356x over previous
#include <cuda_runtime.h>
#include <cstdint>

#define LL   2
#define TT   512
#define BB   128
#define CLSZ 8
#define NCL  16
#define NTHR 512

// ---------------- smem layout (float indices) ----------------
#define OFF_U    0          // [128 col][260 pad h] tf32 bits   33280
#define OFF_HB   33280      // [2 parity][8 n][260 pad h]        4160
#define OFF_OUT  37440      // [2 parity][8 b * 32 k]             512
#define OFF_PRE  37952      // [2 kh][128 col][9 pad n]          2304
#define OFF_WX   40256      // [128 col][4 f]                     512
#define OFF_WB   40768      // [128 col]                          128
#define OFF_FW   40896      // [256 k][4 f]                      1024
#define OFF_FB   41920      // [4]                                  4
#define OFF_FLAG 41924      // [8] int step flags                   8
#define SMEM_FLOATS 41932
#define SMEM_BYTES (SMEM_FLOATS * 4)

// layer-1 output scratch, TRANSPOSED: [B][T][4]
__device__ float g_y1[BB * TT * 4];

typedef unsigned long long ull;

__device__ __forceinline__ uint32_t smem_u32(const void* p) {
    uint32_t a;
    asm("{ .reg .u64 t; cvta.to.shared.u64 t, %1; cvt.u32.u64 %0, t; }"
        : "=r"(a) : "l"(p));
    return a;
}
__device__ __forceinline__ void cluster_sync() {
    asm volatile("barrier.cluster.arrive.aligned;" ::: "memory");
    asm volatile("barrier.cluster.wait.aligned;" ::: "memory");
}
__device__ __forceinline__ float fsig(float x) {
    float e, r;
    asm("ex2.approx.f32 %0, %1;" : "=f"(e) : "f"(x * -1.4426950408889634f));
    asm("rcp.approx.f32 %0, %1;" : "=f"(r) : "f"(1.0f + e));
    return r;
}
__device__ __forceinline__ float ftanh(float x) {
    float e, r;
    asm("ex2.approx.f32 %0, %1;" : "=f"(e) : "f"(x * -2.8853900817779268f));
    asm("rcp.approx.f32 %0, %1;" : "=f"(r) : "f"(1.0f + e));
    return __fmaf_rn(2.0f, r, -1.0f);
}
__device__ __forceinline__ uint32_t f2tf32(float x) {
    uint32_t u;
    asm("cvt.rna.tf32.f32 %0, %1;" : "=r"(u) : "f"(x));
    return u;
}
__device__ __forceinline__ void flag_spin(uint32_t fa, int target) {
    int v;
    do {
        asm volatile("ld.volatile.shared.b32 %0, [%1];" : "=r"(v) : "r"(fa));
    } while (v < target);
}
__device__ __forceinline__ void mma_tf32(float& d0, float& d1, float& d2, float& d3,
                                         uint32_t a0, uint32_t a1, uint32_t a2, uint32_t a3,
                                         uint32_t b0, uint32_t b1) {
    asm("mma.sync.aligned.m16n8k8.row.col.f32.tf32.tf32.f32 "
        "{%0,%1,%2,%3},{%4,%5,%6,%7},{%8,%9},{%0,%1,%2,%3};"
        : "+f"(d0), "+f"(d1), "+f"(d2), "+f"(d3)
        : "r"(a0), "r"(a1), "r"(a2), "r"(a3), "r"(b0), "r"(b1));
}

#define QNEG_MASK 0x284E

__global__ void __launch_bounds__(NTHR, 1) __cluster_dims__(CLSZ, 1, 1)
qlstm_kernel(const float* __restrict__ x,
             const float* __restrict__ Wxr, const float* __restrict__ Wxi,
             const float* __restrict__ Wxj, const float* __restrict__ Wxk,
             const float* __restrict__ Wxb,
             const float* __restrict__ Ur,  const float* __restrict__ Ui,
             const float* __restrict__ Uj,  const float* __restrict__ Uk,
             const float* __restrict__ fcw, const float* __restrict__ fcb,
             float* __restrict__ out)
{
    extern __shared__ float sm[];
    float* sU   = sm + OFF_U;
    float* sHB  = sm + OFF_HB;     // + parity*2080
    float* sOut = sm + OFF_OUT;    // + parity*256
    float* sPre = sm + OFF_PRE;
    float* sWx  = sm + OFF_WX;
    float* sWb  = sm + OFF_WB;
    float* sFW  = sm + OFF_FW;
    float* sFB  = sm + OFF_FB;

    const int tid  = threadIdx.x;
    const int lane = tid & 31;
    const int wid  = tid >> 5;
    const int r    = blockIdx.x & 7;
    const int cid  = blockIdx.x >> 3;
    const uint32_t sbase = smem_u32(sm);

    // mma role (all 16 warps): warp = (col-tile ct 0..7, K-half kh 0..1)
    const int ct = wid & 7;
    const int kh = wid >> 3;
    const int mr = lane >> 2;
    const int mc = lane & 3;

    // act role (warps 0..3): cell k = lane, batches b0,b1
    const int k  = lane;
    const int b0 = wid * 2;
    const int b1 = b0 + 1;

    // pull role (warps 4..11): source rank pj
    const int pj = wid - 4;

    // ---- one-time init ----
    if (tid < 8) ((int*)(sm + OFF_FLAG))[tid] = 0;
    __syncthreads();
    cluster_sync();

    float2 creg;

    for (int l = 0; l < LL; l++) {
        __syncthreads();

        // ---- gather U slice (tf32-rounded), layout sU[col][260 pad h] ----
        for (int idx = tid; idx < 4 * 256 * 32; idx += NTHR) {
            int g   = idx >> 13;
            int rem = idx & 8191;
            int h   = rem >> 5;
            int kl  = rem & 31;
            int kg  = r * 32 + kl;
            int hb  = h >> 6, n = h & 63;
            int cb  = kg >> 6, m = kg & 63;
            int sel = hb ^ cb;
            float sgn = ((QNEG_MASK >> (cb * 4 + hb)) & 1) ? -1.0f : 1.0f;
            const float* cp = (sel == 0) ? Ur : (sel == 1) ? Ui : (sel == 2) ? Uj : Uk;
            float v = sgn * __ldg(&cp[((l * 4 + g) * 64 + n) * 64 + m]);
            sU[(g * 32 + kl) * 260 + h] = __uint_as_float(f2tf32(v));
        }
        for (int idx = tid; idx < 512; idx += NTHR) {
            int g  = idx >> 7;
            int f  = (idx >> 5) & 3;
            int kl = idx & 31;
            int kg = r * 32 + kl;
            int cb = kg >> 6, m = kg & 63;
            int sel = f ^ cb;
            float sgn = ((QNEG_MASK >> (cb * 4 + f)) & 1) ? -1.0f : 1.0f;
            const float* cp = (sel == 0) ? Wxr : (sel == 1) ? Wxi : (sel == 2) ? Wxj : Wxk;
            sWx[(g * 32 + kl) * 4 + f] = sgn * __ldg(&cp[(l * 4 + g) * 64 + m]);
        }
        for (int idx = tid; idx < 128; idx += NTHR) {
            int g = idx >> 5, kl = idx & 31;
            sWb[idx] = Wxb[(l * 4 + g) * 256 + r * 32 + kl];
        }
        for (int idx = tid; idx < 1024; idx += NTHR)
            sFW[idx] = fcw[l * 1024 + idx];
        if (tid < 4) sFB[tid] = fcb[l * 4 + tid];
        // zero both h parity buffers (h_0 = 0)
        for (int i = tid; i < 2 * 2080; i += NTHR) sHB[i] = 0.0f;
        creg = make_float2(0.0f, 0.0f);
        __syncthreads();

        // ---- preload this warp's U A-fragments into registers (per layer) ----
        uint32_t Afr[16][4];
        {
            const int row0 = ct * 16 + mr;
            const int kb0  = kh * 128 + mc;
#pragma unroll
            for (int kt = 0; kt < 16; kt++) {
                int kb = kb0 + kt * 8;
                Afr[kt][0] = __float_as_uint(sU[row0 * 260 + kb]);
                Afr[kt][1] = __float_as_uint(sU[(row0 + 8) * 260 + kb]);
                Afr[kt][2] = __float_as_uint(sU[row0 * 260 + kb + 4]);
                Afr[kt][3] = __float_as_uint(sU[(row0 + 8) * 260 + kb + 4]);
            }
        }

        const float4* xp = (const float4*)((l == 0) ? x : g_y1);  // [B][T][4]

        for (int t = 0; t < TT; t++) {
            const int cur = t & 1;
            const int nxt = cur ^ 1;

            // ---- act warps: prefetch x early (hidden under MMA) ----
            float4 xv0, xv1;
            if (wid < 4) {
                xv0 = __ldg(&xp[(cid * 8 + b0) * TT + t]);
                xv1 = __ldg(&xp[(cid * 8 + b1) * TT + t]);
            }

            // ---- tensor GEMM: D[16c x 8b] += U^T tile @ h_t  (all 16 warps) ----
            {
                float dA0 = 0.f, dA1 = 0.f, dA2 = 0.f, dA3 = 0.f;
                float dB0 = 0.f, dB1 = 0.f, dB2 = 0.f, dB3 = 0.f;
                const float* bp = sHB + cur * 2080 + mr * 260 + kh * 128 + mc;
#pragma unroll
                for (int kt = 0; kt < 8; kt++) {
                    uint32_t bb0 = __float_as_uint(bp[kt * 8]);
                    uint32_t bb1 = __float_as_uint(bp[kt * 8 + 4]);
                    mma_tf32(dA0, dA1, dA2, dA3,
                             Afr[kt][0], Afr[kt][1], Afr[kt][2], Afr[kt][3], bb0, bb1);
                }
#pragma unroll
                for (int kt = 8; kt < 16; kt++) {
                    uint32_t bb0 = __float_as_uint(bp[kt * 8]);
                    uint32_t bb1 = __float_as_uint(bp[kt * 8 + 4]);
                    mma_tf32(dB0, dB1, dB2, dB3,
                             Afr[kt][0], Afr[kt][1], Afr[kt][2], Afr[kt][3], bb0, bb1);
                }
                const int colA = ct * 16 + mr;
                const int nn   = mc * 2;
                float* p0 = sPre + kh * 1152 + colA * 9 + nn;
                float* p1 = sPre + kh * 1152 + (colA + 8) * 9 + nn;
                p0[0] = dA0 + dB0; p0[1] = dA1 + dB1;
                p1[0] = dA2 + dB2; p1[1] = dA3 + dB3;
            }
            __syncthreads();   // sPre complete

            if (wid < 4) {
                // ---- act: combine K-halves + gates + cell update ----
                float pre0[4], pre1[4];
#pragma unroll
                for (int g = 0; g < 4; g++) {
                    int col = g * 32 + k;
                    float4 wx = *(const float4*)&sWx[col * 4];
                    float wb  = sWb[col];
                    float base0 = sPre[col * 9 + b0] + sPre[1152 + col * 9 + b0];
                    float base1 = sPre[col * 9 + b1] + sPre[1152 + col * 9 + b1];
                    pre0[g] = base0 + wb + xv0.x * wx.x + xv0.y * wx.y
                                         + xv0.z * wx.z + xv0.w * wx.w;
                    pre1[g] = base1 + wb + xv1.x * wx.x + xv1.y * wx.y
                                         + xv1.z * wx.z + xv1.w * wx.w;
                }
                {
                    float ft = fsig(pre0[0]), it = fsig(pre0[1]);
                    float ot = fsig(pre0[2]), cc = ftanh(pre0[3]);
                    float c = it * cc + ft * creg.x;
                    creg.x = c;
                    sOut[cur * 256 + b0 * 32 + k] =
                        __uint_as_float(f2tf32(ot * ftanh(c)));
                }
                {
                    float ft = fsig(pre1[0]), it = fsig(pre1[1]);
                    float ot = fsig(pre1[2]), cc = ftanh(pre1[3]);
                    float c = it * cc + ft * creg.y;
                    creg.y = c;
                    sOut[cur * 256 + b1 * 32 + k] =
                        __uint_as_float(f2tf32(ot * ftanh(c)));
                }
                // act-warps-only barrier (drains sOut STS), then publish EARLY
                asm volatile("bar.sync 1, 128;" ::: "memory");
                if (tid == 0) {
                    const int gs = l * TT + t + 1;
                    uint32_t fa = sbase + (OFF_FLAG + r) * 4;
#pragma unroll
                    for (int j = 0; j < CLSZ; j++) {
                        uint32_t ra;
                        asm("mapa.shared::cluster.u32 %0, %1, %2;"
                            : "=r"(ra) : "r"(fa), "r"(j));
                        asm volatile("st.shared::cluster.b32 [%0], %1;"
                                     :: "r"(ra), "r"(gs) : "memory");
                    }
                }
            } else if (wid < 12) {
                // ---- pull warp for rank pj: spin, then fetch its slice ----
                const int target = l * TT + t + 1;
                if (lane == 0)
                    flag_spin(sbase + (OFF_FLAG + pj) * 4, target);
                __syncwarp();
#pragma unroll
                for (int q = 0; q < 4; q++) {
                    int idx = lane + 32 * q;          // 0..127 b64 units
                    int b   = idx >> 4;
                    int ko  = (idx & 15) * 2;
                    uint32_t so = sbase +
                        (uint32_t)(OFF_OUT + cur * 256 + b * 32 + ko) * 4;
                    uint32_t ra;
                    asm("mapa.shared::cluster.u32 %0, %1, %2;"
                        : "=r"(ra) : "r"(so), "r"(pj));
                    ull v;
                    asm volatile("ld.shared::cluster.b64 %0, [%1];"
                                 : "=l"(v) : "r"(ra) : "memory");
                    asm volatile("st.shared.b64 [%0], %1;"
                                 :: "r"(sbase + (uint32_t)(OFF_HB + nxt * 2080 +
                                        b * 260 + pj * 32 + ko) * 4),
                                    "l"(v) : "memory");
                }
            } else if (l == 0 && wid == 15 && t > 0) {
                // ---- y-warp: y_{t-1} = norm(fco(h_t)) from sHB[cur] ----
                const float* hb = sHB + cur * 2080;
                float s0 = 0.f, s1 = 0.f, s2 = 0.f, s3 = 0.f;
#pragma unroll
                for (int i = 0; i < 8; i++) {
                    int kk = lane + i * 32;
                    float hv = hb[r * 260 + kk];
                    float4 fw = *(const float4*)&sFW[kk * 4];
                    s0 += hv * fw.x; s1 += hv * fw.y;
                    s2 += hv * fw.z; s3 += hv * fw.w;
                }
#pragma unroll
                for (int m = 16; m >= 1; m >>= 1) {
                    s0 += __shfl_xor_sync(0xffffffffu, s0, m);
                    s1 += __shfl_xor_sync(0xffffffffu, s1, m);
                    s2 += __shfl_xor_sync(0xffffffffu, s2, m);
                    s3 += __shfl_xor_sync(0xffffffffu, s3, m);
                }
                if (lane == 0) {
                    s0 += sFB[0]; s1 += sFB[1]; s2 += sFB[2]; s3 += sFB[3];
                    float nn = s0*s0 + s1*s1 + s2*s2 + s3*s3;
                    float iv = 1.0f / fmaxf(sqrtf(nn), 1e-12f);
                    ((float4*)g_y1)[(cid * 8 + r) * TT + (t - 1)] =
                        make_float4(s0*iv, s1*iv, s2*iv, s3*iv);
                }
            }

            __syncthreads();   // sHB[nxt] = h_{t+1} complete
        } // t

        // ---- final y from h_T (in sHB[TT&1 = 0]) ----
        if (wid == 15) {
            const float* hb = sHB + ((TT) & 1) * 2080;
            float s0 = 0.f, s1 = 0.f, s2 = 0.f, s3 = 0.f;
#pragma unroll
            for (int i = 0; i < 8; i++) {
                int kk = lane + i * 32;
                float hv = hb[r * 260 + kk];
                float4 fw = *(const float4*)&sFW[kk * 4];
                s0 += hv * fw.x; s1 += hv * fw.y;
                s2 += hv * fw.z; s3 += hv * fw.w;
            }
#pragma unroll
            for (int m = 16; m >= 1; m >>= 1) {
                s0 += __shfl_xor_sync(0xffffffffu, s0, m);
                s1 += __shfl_xor_sync(0xffffffffu, s1, m);
                s2 += __shfl_xor_sync(0xffffffffu, s2, m);
                s3 += __shfl_xor_sync(0xffffffffu, s3, m);
            }
            if (lane == 0) {
                s0 += sFB[0]; s1 += sFB[1]; s2 += sFB[2]; s3 += sFB[3];
                float nn = s0*s0 + s1*s1 + s2*s2 + s3*s3;
                float iv = 1.0f / fmaxf(sqrtf(nn), 1e-12f);
                if (l == 0) {
                    ((float4*)g_y1)[(cid * 8 + r) * TT + (TT - 1)] =
                        make_float4(s0*iv, s1*iv, s2*iv, s3*iv);
                } else {
                    ((float4*)out)[cid * 8 + r] =
                        make_float4(s0*iv, s1*iv, s2*iv, s3*iv);
                }
            }
        }
        cluster_sync();   // g_y1 visible cluster-wide before next layer
    } // l

    cluster_sync();   // no CTA exits while peers may still touch its SMEM
}

extern "C" void kernel_launch(void* const* d_in, const int* in_sizes, int n_in,
                              void* d_out, int out_size)
{
    (void)in_sizes; (void)n_in; (void)out_size;
    cudaFuncSetAttribute(qlstm_kernel,
                         cudaFuncAttributeMaxDynamicSharedMemorySize, SMEM_BYTES);
    qlstm_kernel<<<NCL * CLSZ, NTHR, SMEM_BYTES>>>(
        (const float*)d_in[0],
        (const float*)d_in[1], (const float*)d_in[2],
        (const float*)d_in[3], (const float*)d_in[4],
        (const float*)d_in[5],
        (const float*)d_in[6], (const float*)d_in[7],
        (const float*)d_in[8], (const float*)d_in[9],
        (const float*)d_in[10], (const float*)d_in[11],
        (float*)d_out);
}